// round 9
// baseline (speedup 1.0000x reference)
#include <cuda_runtime.h>
#include <mma.h>
#include <math.h>
#include <stdint.h>

using namespace nvcuda;

#define EMBED   256
#define PAIRS   15
#define TOKENS  16384            // 32 * 512
#define KPAIR   512              // 2 * EMBED
#define KFINAL  3840             // 15 * 256

#define BM 128
#define BN 128
#define BK 16
#define LDA 20                   // 16 + 4 pad floats (80B rows, 16B-aligned)
#define LDB 132                  // 128 + 4 pad floats (528B rows, 16B-aligned)
#define LDC 132
#define NTH 256
#define NSTAGE 4

#define A_ST (BM * LDA)          // 2560 floats / stage (10240 B)
#define B_ST (BK * LDB)          // 2112 floats / stage (8448 B)

// pair kernel: A double-buffer (2) + B 4-stage
#define SMEM_PAIR_FLOATS  (2 * A_ST + NSTAGE * B_ST)   // 13568 fl = 54272 B
// final kernel: A 4-stage + B 4-stage
#define SMEM_FIN_FLOATS   (NSTAGE * A_ST + NSTAGE * B_ST) // 18688 fl = 74752 B

// ---- global scratch (allocation-free) ----
__device__ float g_H [(size_t)PAIRS * TOKENS * EMBED];   // tanh outputs, tf32-RN-rounded
__device__ float g_Wp[(size_t)PAIRS * KPAIR * EMBED];    // W_pair, tf32-RN-rounded
__device__ float g_Wf[(size_t)KFINAL * EMBED];           // W_final, tf32-RN-rounded

__constant__ int c_PI[PAIRS] = {0,0,0,0,0,1,1,1,1,2,2,2,3,3,4};
__constant__ int c_PJ[PAIRS] = {1,2,3,4,5,2,3,4,5,3,4,5,4,5,5};

__device__ __forceinline__ uint32_t smem_u32(const void* p) {
    uint32_t a;
    asm("{ .reg .u64 t; cvta.to.shared.u64 t, %1; cvt.u32.u64 %0, t; }" : "=r"(a) : "l"(p));
    return a;
}
#define CP16(dst, src) \
    asm volatile("cp.async.cg.shared.global [%0], [%1], 16;" :: "r"(dst), "l"(src) : "memory")
#define CP_COMMIT()  asm volatile("cp.async.commit_group;" ::: "memory")
#define CP_WAIT(n)   asm volatile("cp.async.wait_group %0;" :: "n"(n) : "memory")

#define CVT4(dst, v)                                   \
    do {                                               \
        (dst)[0] = wmma::__float_to_tf32((v).x);       \
        (dst)[1] = wmma::__float_to_tf32((v).y);       \
        (dst)[2] = wmma::__float_to_tf32((v).z);       \
        (dst)[3] = wmma::__float_to_tf32((v).w);       \
    } while (0)

// ---------------------------------------------------------------------------
// Pre-pass: tf32-RN-round weights into global scratch (grid-stride float4).
// ---------------------------------------------------------------------------
__global__ void __launch_bounds__(NTH)
round_copy(const float* __restrict__ src, float* __restrict__ dst, int n4) {
    for (int i = blockIdx.x * NTH + threadIdx.x; i < n4; i += gridDim.x * NTH) {
        float4 v = ((const float4*)src)[i];
        v.x = wmma::__float_to_tf32(v.x);
        v.y = wmma::__float_to_tf32(v.y);
        v.z = wmma::__float_to_tf32(v.z);
        v.w = wmma::__float_to_tf32(v.w);
        ((float4*)dst)[i] = v;
    }
}

// ---------------------------------------------------------------------------
// Warp-tile compute: 64x32 per warp, 2 kk-steps of m16n16k8 tf32.
// ---------------------------------------------------------------------------
#define COMPUTE_STAGE(Abuf, Bst)                                                          \
    do {                                                                                  \
        _Pragma("unroll")                                                                 \
        for (int kk = 0; kk < BK; kk += 8) {                                              \
            wmma::fragment<wmma::matrix_a, 16, 16, 8, wmma::precision::tf32,              \
                           wmma::row_major> af[4];                                        \
            wmma::fragment<wmma::matrix_b, 16, 16, 8, wmma::precision::tf32,              \
                           wmma::row_major> bf[2];                                        \
            _Pragma("unroll")                                                             \
            for (int a = 0; a < 4; a++)                                                   \
                wmma::load_matrix_sync(af[a], (Abuf) + (a * 16) * LDA + kk, LDA);         \
            _Pragma("unroll")                                                             \
            for (int b = 0; b < 2; b++)                                                   \
                wmma::load_matrix_sync(bf[b], (Bst) + kk * LDB + b * 16, LDB);            \
            _Pragma("unroll")                                                             \
            for (int a = 0; a < 4; a++)                                                   \
                _Pragma("unroll")                                                         \
                for (int b = 0; b < 2; b++)                                               \
                    wmma::mma_sync(cf[a][b], af[a], bf[b], cf[a][b]);                     \
        }                                                                                 \
    } while (0)

// ---------------------------------------------------------------------------
// Kernel 1: H[p] = tf32rn( tanh(concat(F_i,F_j) @ W_pair[p] + b_pair[p]) )
// A (features): LDG + RN-convert + STS, double buffered.
// B (g_Wp, pre-rounded): cp.async.cg, 4 stages.
// ---------------------------------------------------------------------------
__global__ void __launch_bounds__(NTH, 2)
pair_gemm_v3(const float* __restrict__ features,
             const float* __restrict__ b_pair,
             const int*   __restrict__ NAS)
{
    const int p  = blockIdx.z;
    const int fi = c_PI[p], fj = c_PJ[p];
    if (((fi < 2) ? 1 : NAS[fi]) * ((fj < 2) ? 1 : NAS[fj]) == 0) return;

    extern __shared__ __align__(16) float sm[];
    float* As = sm;                      // 2 x A_ST
    float* Bs = sm + 2 * A_ST;           // NSTAGE x B_ST
    const uint32_t sB = smem_u32(Bs);

    const int tid  = threadIdx.x;
    const int warp = tid >> 5;
    const int wm   = warp & 1;
    const int wn   = warp >> 1;
    const int tok0 = blockIdx.x * BM;
    const int n0   = blockIdx.y * BN;

    const float* featI = features + ((size_t)fi * TOKENS + tok0) * EMBED;
    const float* featJ = features + ((size_t)fj * TOKENS + tok0) * EMBED;
    const float* Wp    = g_Wp + (size_t)p * KPAIR * EMBED + n0;

    // per-thread load coords
    const int arow = tid >> 2, ac = (tid & 3);    // A: 128 rows x 4 float4; 2/thread
    const int brow = tid >> 5, bc = (tid & 31);   // B: 16 rows x 32 float4; 2/thread (rows brow, brow+8)

    const int NC = KPAIR / BK;   // 32

    // ---- prologue ----
    #pragma unroll
    for (int i = 0; i < 2; i++) {                 // A stage 0 (LDG+CVT+STS)
        int q = tid + i * NTH, row = q >> 2, c = q & 3;
        float4 v = *(const float4*)(featI + (size_t)row * EMBED + c * 4);
        CVT4(As + row * LDA + c * 4, v);
    }
    #pragma unroll
    for (int s = 0; s < NSTAGE - 1; s++) {        // B stages 0..2
        #pragma unroll
        for (int i = 0; i < 2; i++) {
            int q = tid + i * NTH, row = q >> 5, c = q & 31;
            CP16(sB + (s * B_ST + row * LDB) * 4 + c * 16,
                 Wp + (size_t)(s * BK + row) * EMBED + c * 4);
        }
        CP_COMMIT();
    }
    CP_WAIT(2);
    __syncthreads();

    wmma::fragment<wmma::accumulator, 16, 16, 8, float> cf[4][2];
    #pragma unroll
    for (int a = 0; a < 4; a++)
        #pragma unroll
        for (int b = 0; b < 2; b++)
            wmma::fill_fragment(cf[a][b], 0.0f);

    // ---- main loop ----
    for (int t = 0; t < NC; t++) {
        float4 aR[2];
        const bool haveA = (t + 1 < NC);
        if (haveA) {
            const int k0 = (t + 1) * BK;
            const float* Asrc = (k0 < EMBED) ? (featI + k0) : (featJ + (k0 - EMBED));
            #pragma unroll
            for (int i = 0; i < 2; i++) {
                int q = tid + i * NTH, row = q >> 2, c = q & 3;
                aR[i] = *(const float4*)(Asrc + (size_t)row * EMBED + c * 4);
            }
        }
        if (t + NSTAGE - 1 < NC) {
            const int k0 = (t + NSTAGE - 1) * BK;
            const int s  = (t + NSTAGE - 1) & (NSTAGE - 1);
            #pragma unroll
            for (int i = 0; i < 2; i++) {
                int q = tid + i * NTH, row = q >> 5, c = q & 31;
                CP16(sB + (s * B_ST + row * LDB) * 4 + c * 16,
                     Wp + (size_t)(k0 + row) * EMBED + c * 4);
            }
        }
        CP_COMMIT();

        const float* Abuf = As + (t & 1) * A_ST + wm * 64 * LDA;
        const float* Bst  = Bs + (t & (NSTAGE - 1)) * B_ST + wn * 32;
        COMPUTE_STAGE(Abuf, Bst);

        if (haveA) {
            float* Ad = As + ((t + 1) & 1) * A_ST;
            #pragma unroll
            for (int i = 0; i < 2; i++) {
                int q = tid + i * NTH, row = q >> 2, c = q & 3;
                CVT4(Ad + row * LDA + c * 4, aR[i]);
            }
        }
        CP_WAIT(2);
        __syncthreads();
    }
    CP_WAIT(0);
    __syncthreads();

    // ---- epilogue: stage C via smem halves; bias + tanh + tf32-RN; write g_H ----
    float*       Hout = g_H    + ((size_t)p * TOKENS + tok0) * EMBED + n0;
    const float* bp   = b_pair + p * EMBED + n0;
    float* Cs = sm;
    #pragma unroll
    for (int half = 0; half < 2; half++) {
        if (wm == half) {
            #pragma unroll
            for (int a = 0; a < 4; a++)
                #pragma unroll
                for (int b = 0; b < 2; b++)
                    wmma::store_matrix_sync(Cs + (a * 16) * LDC + wn * 32 + b * 16,
                                            cf[a][b], LDC, wmma::mem_row_major);
        }
        __syncthreads();
        #pragma unroll
        for (int i = 0; i < 8; i++) {
            int q = tid + i * NTH, row = q >> 5, c4 = (q & 31) * 4;
            float4 v  = *(float4*)(Cs + row * LDC + c4);
            float4 bb = *(const float4*)(bp + c4);
            float4 o;
            o.x = wmma::__float_to_tf32(tanhf(v.x + bb.x));
            o.y = wmma::__float_to_tf32(tanhf(v.y + bb.y));
            o.z = wmma::__float_to_tf32(tanhf(v.z + bb.z));
            o.w = wmma::__float_to_tf32(tanhf(v.w + bb.w));
            *(float4*)(Hout + (size_t)(half * 64 + row) * EMBED + c4) = o;
        }
        __syncthreads();
    }
}

// ---------------------------------------------------------------------------
// Kernel 2: out = H_flat @ W_final + b_final  (active pairs' K-chunks only)
// A (g_H) and B (g_Wf) both pre-rounded -> raw cp.async, 4 stages each.
// ---------------------------------------------------------------------------
__global__ void __launch_bounds__(NTH, 2)
final_gemm_v3(const float* __restrict__ b_final,
              const int*   __restrict__ NAS,
              float*       __restrict__ out)
{
    extern __shared__ __align__(16) float sm[];
    float* As = sm;                       // NSTAGE x A_ST
    float* Bs = sm + NSTAGE * A_ST;       // NSTAGE x B_ST
    const uint32_t sA = smem_u32(As);
    const uint32_t sB = smem_u32(Bs);

    const int tid  = threadIdx.x;
    const int warp = tid >> 5;
    const int wm   = warp & 1;
    const int wn   = warp >> 1;
    const int tok0 = blockIdx.x * BM;
    const int n0   = blockIdx.y * BN;

    int nas_eff[6];
    #pragma unroll
    for (int f = 0; f < 6; f++) nas_eff[f] = (f < 2) ? 1 : NAS[f];
    int plist[PAIRS], np = 0;
    #pragma unroll
    for (int p = 0; p < PAIRS; p++)
        if (nas_eff[c_PI[p]] * nas_eff[c_PJ[p]] != 0) plist[np++] = p;
    const int TPP = EMBED / BK;          // 16
    const int NC  = np * TPP;            // >= 16

    const int arow = tid >> 2, ac = (tid & 3);
    const int brow = tid >> 5, bc = (tid & 31);

    // issue one full (A+B) stage t into slot s
    #define ISSUE_STAGE(t_, s_)                                                        \
        do {                                                                           \
            const int _p    = plist[(t_) >> 4];                                        \
            const int _koff = ((t_) & 15) * BK;                                        \
            const float* _Asrc = g_H + ((size_t)_p * TOKENS + tok0) * EMBED + _koff;   \
            const float* _Bsrc = g_Wf + (size_t)(_p * EMBED + _koff) * EMBED + n0;     \
            _Pragma("unroll")                                                          \
            for (int i = 0; i < 2; i++) {                                              \
                int q = tid + i * NTH, row = q >> 2, c = q & 3;                        \
                CP16(sA + ((s_) * A_ST + row * LDA) * 4 + c * 16,                      \
                     _Asrc + (size_t)row * EMBED + c * 4);                             \
            }                                                                          \
            _Pragma("unroll")                                                          \
            for (int i = 0; i < 2; i++) {                                              \
                int q = tid + i * NTH, row = q >> 5, c = q & 31;                       \
                CP16(sB + ((s_) * B_ST + row * LDB) * 4 + c * 16,                      \
                     _Bsrc + (size_t)row * EMBED + c * 4);                             \
            }                                                                          \
        } while (0)

    // ---- prologue: stages 0..2 ----
    #pragma unroll
    for (int s = 0; s < NSTAGE - 1; s++) {
        ISSUE_STAGE(s, s);
        CP_COMMIT();
    }
    CP_WAIT(2);
    __syncthreads();

    wmma::fragment<wmma::accumulator, 16, 16, 8, float> cf[4][2];
    #pragma unroll
    for (int a = 0; a < 4; a++)
        #pragma unroll
        for (int b = 0; b < 2; b++)
            wmma::fill_fragment(cf[a][b], 0.0f);

    // ---- main loop ----
    for (int t = 0; t < NC; t++) {
        if (t + NSTAGE - 1 < NC)
            ISSUE_STAGE(t + NSTAGE - 1, (t + NSTAGE - 1) & (NSTAGE - 1));
        CP_COMMIT();

        const float* Abuf = As + (t & (NSTAGE - 1)) * A_ST + wm * 64 * LDA;
        const float* Bst  = Bs + (t & (NSTAGE - 1)) * B_ST + wn * 32;
        COMPUTE_STAGE(Abuf, Bst);

        CP_WAIT(2);
        __syncthreads();
    }
    CP_WAIT(0);
    __syncthreads();

    // ---- epilogue: bias only ----
    float*       Optr = out     + (size_t)tok0 * EMBED + n0;
    const float* bf_  = b_final + n0;
    float* Cs = sm;
    #pragma unroll
    for (int half = 0; half < 2; half++) {
        if (wm == half) {
            #pragma unroll
            for (int a = 0; a < 4; a++)
                #pragma unroll
                for (int b = 0; b < 2; b++)
                    wmma::store_matrix_sync(Cs + (a * 16) * LDC + wn * 32 + b * 16,
                                            cf[a][b], LDC, wmma::mem_row_major);
        }
        __syncthreads();
        #pragma unroll
        for (int i = 0; i < 8; i++) {
            int q = tid + i * NTH, row = q >> 5, c4 = (q & 31) * 4;
            float4 v  = *(float4*)(Cs + row * LDC + c4);
            float4 bb = *(const float4*)(bf_ + c4);
            float4 o;
            o.x = v.x + bb.x;
            o.y = v.y + bb.y;
            o.z = v.z + bb.z;
            o.w = v.w + bb.w;
            *(float4*)(Optr + (size_t)(half * 64 + row) * EMBED + c4) = o;
        }
        __syncthreads();
    }
    #undef ISSUE_STAGE
}

// ---------------------------------------------------------------------------
extern "C" void kernel_launch(void* const* d_in, const int* in_sizes, int n_in,
                              void* d_out, int out_size)
{
    const float* features = (const float*)d_in[0];
    const float* W_pair   = (const float*)d_in[1];
    const float* b_pair   = (const float*)d_in[2];
    const float* W_final  = (const float*)d_in[3];
    const float* b_final  = (const float*)d_in[4];
    const int*   NAS      = (const int*)  d_in[5];
    float*       out      = (float*)d_out;

    static float* wp_dst = nullptr;
    static float* wf_dst = nullptr;
    if (!wp_dst) { cudaGetSymbolAddress((void**)&wp_dst, g_Wp);
                   cudaGetSymbolAddress((void**)&wf_dst, g_Wf); }

    cudaFuncSetAttribute(pair_gemm_v3,  cudaFuncAttributeMaxDynamicSharedMemorySize,
                         SMEM_PAIR_FLOATS * 4);
    cudaFuncSetAttribute(final_gemm_v3, cudaFuncAttributeMaxDynamicSharedMemorySize,
                         SMEM_FIN_FLOATS * 4);

    round_copy<<<592, NTH>>>(W_pair,  wp_dst, PAIRS * KPAIR * EMBED / 4);
    round_copy<<<592, NTH>>>(W_final, wf_dst, KFINAL * EMBED / 4);

    dim3 block(NTH);
    dim3 grid1(TOKENS / BM, EMBED / BN, PAIRS);   // 128 x 2 x 15
    pair_gemm_v3<<<grid1, block, SMEM_PAIR_FLOATS * 4>>>(features, b_pair, NAS);

    dim3 grid2(TOKENS / BM, EMBED / BN);          // 128 x 2
    final_gemm_v3<<<grid2, block, SMEM_FIN_FLOATS * 4>>>(b_final, NAS, out);
}